// round 1
// baseline (speedup 1.0000x reference)
#include <cuda_runtime.h>
#include <math.h>

#define EPSV 1e-5f

static const int BATCH = 4;
static const int CCH   = 512;
static const int NSP   = 4096;   // H*W

// ---------------- scratch (device globals; no runtime allocation) ----------------
__device__ float g_xn [(size_t)4 * 512 * 4096];
__device__ float g_q  [(size_t)4 * 512 * 4096];
__device__ float g_k  [(size_t)4 * 512 * 4096];
__device__ float g_v  [(size_t)4 * 512 * 4096];
__device__ float g_o  [(size_t)4 * 512 * 4096];
__device__ float g_cf [(size_t)4 * 512 * 4096];
__device__ float g_sf [(size_t)4 * 512 * 4096];
__device__ float g_attn[(size_t)4 * 4096 * 4096];

// ---------------- MVN: per-row mean/var normalize (unbiased var, ddof=1) ----------------
__global__ void mvn_kernel(const float* __restrict__ x, float* __restrict__ y, int n) {
    const float* xr = x + (size_t)blockIdx.x * n;
    float*       yr = y + (size_t)blockIdx.x * n;
    int tid = threadIdx.x;
    float s = 0.f, s2 = 0.f;
    for (int i = tid; i < n; i += blockDim.x) {
        float v = xr[i];
        s += v; s2 += v * v;
    }
    __shared__ float sh0[256];
    __shared__ float sh1[256];
    sh0[tid] = s; sh1[tid] = s2;
    __syncthreads();
    for (int o = 128; o > 0; o >>= 1) {
        if (tid < o) { sh0[tid] += sh0[tid + o]; sh1[tid] += sh1[tid + o]; }
        __syncthreads();
    }
    float mean = sh0[0] / (float)n;
    float var  = (sh1[0] - (float)n * mean * mean) / (float)(n - 1);
    float inv  = rsqrtf(var + EPSV);
    for (int i = tid; i < n; i += blockDim.x) {
        yr[i] = (xr[i] - mean) * inv;
    }
}

// ---------------- row softmax (in place) ----------------
__global__ void softmax_kernel(float* __restrict__ data, int n) {
    float* r = data + (size_t)blockIdx.x * n;
    int tid = threadIdx.x;
    __shared__ float sh[256];
    float m = -1e30f;
    for (int i = tid; i < n; i += blockDim.x) m = fmaxf(m, r[i]);
    sh[tid] = m; __syncthreads();
    for (int o = 128; o > 0; o >>= 1) {
        if (tid < o) sh[tid] = fmaxf(sh[tid], sh[tid + o]);
        __syncthreads();
    }
    float mx = sh[0];
    __syncthreads();
    float s = 0.f;
    for (int i = tid; i < n; i += blockDim.x) {
        float e = expf(r[i] - mx);
        r[i] = e;
        s += e;
    }
    sh[tid] = s; __syncthreads();
    for (int o = 128; o > 0; o >>= 1) {
        if (tid < o) sh[tid] += sh[tid + o];
        __syncthreads();
    }
    float inv = 1.f / sh[0];
    for (int i = tid; i < n; i += blockDim.x) r[i] *= inv;
}

// ---------------- generic-stride batched SGEMM, 128x128x8 tile, 8x8/thread ----------------
// C[b][m][n] = sum_k A(m,k) * B(k,n) + bias[m] + res[b][m][n]
// A(m,k) = A[b*aBatch + m*sam + k*sak], B(k,n) = B[b*bBatch + k*sbk + n*sbn]
// Requires M%128==0, N%128==0, K%8==0.
__global__ __launch_bounds__(256) void gemm_kernel(
    const float* __restrict__ A, const float* __restrict__ Bp, float* __restrict__ C,
    long long aBatch, long long sam, long long sak,
    long long bBatch, long long sbk, long long sbn,
    long long cBatch,
    const float* __restrict__ bias,
    const float* __restrict__ res, long long rBatch,
    int M, int N, int K)
{
    const int BM = 128, BN = 128, BK = 8, TM = 8, TN = 8;
    __shared__ float As[BK][BM + 4];
    __shared__ float Bs[BK][BN + 4];

    int bz = blockIdx.z;
    A  += (long long)bz * aBatch;
    Bp += (long long)bz * bBatch;
    C  += (long long)bz * cBatch;
    if (res) res += (long long)bz * rBatch;

    int tid = threadIdx.x;
    int m0 = blockIdx.y * BM;
    int n0 = blockIdx.x * BN;
    int ty = tid >> 4;       // 0..15
    int tx = tid & 15;       // 0..15

    bool aK = (sak == 1);
    bool bK = (sbk == 1);

    float acc[TM][TN];
#pragma unroll
    for (int i = 0; i < TM; i++)
#pragma unroll
        for (int j = 0; j < TN; j++) acc[i][j] = 0.f;

    for (int k0 = 0; k0 < K; k0 += BK) {
        // load A tile (BM x BK) -> As[k][m]
#pragma unroll
        for (int i = 0; i < 4; i++) {
            int l = tid + i * 256;
            int mm, kk;
            if (aK) { kk = l & 7; mm = l >> 3; }
            else    { mm = l & 127; kk = l >> 7; }
            As[kk][mm] = A[(long long)(m0 + mm) * sam + (long long)(k0 + kk) * sak];
        }
        // load B tile (BK x BN) -> Bs[k][n]
#pragma unroll
        for (int i = 0; i < 4; i++) {
            int l = tid + i * 256;
            int nn, kk;
            if (bK) { kk = l & 7; nn = l >> 3; }
            else    { nn = l & 127; kk = l >> 7; }
            Bs[kk][nn] = Bp[(long long)(k0 + kk) * sbk + (long long)(n0 + nn) * sbn];
        }
        __syncthreads();

#pragma unroll
        for (int kk = 0; kk < BK; kk++) {
            float ar[TM], br[TN];
#pragma unroll
            for (int i = 0; i < TM; i++) ar[i] = As[kk][ty * TM + i];
#pragma unroll
            for (int j = 0; j < TN; j++) br[j] = Bs[kk][tx * TN + j];
#pragma unroll
            for (int i = 0; i < TM; i++)
#pragma unroll
                for (int j = 0; j < TN; j++) acc[i][j] += ar[i] * br[j];
        }
        __syncthreads();
    }

#pragma unroll
    for (int i = 0; i < TM; i++) {
        int row = m0 + ty * TM + i;
        float bi = bias ? bias[row] : 0.f;
#pragma unroll
        for (int j = 0; j < TN; j++) {
            int col = n0 + tx * TN + j;
            float vv = acc[i][j] + bi;
            if (res) vv += res[(long long)row * N + col];
            C[(long long)row * N + col] = vv;
        }
    }
}

// ---------------- orchestration ----------------
extern "C" void kernel_launch(void* const* d_in, const int* in_sizes, int n_in,
                              void* d_out, int out_size) {
    const float* content = (const float*)d_in[0];
    const float* style   = (const float*)d_in[1];
    const float* csa_w   = (const float*)d_in[2];
    const float* csa_b   = (const float*)d_in[3];
    const float* ssa_w   = (const float*)d_in[4];
    const float* ssa_b   = (const float*)d_in[5];
    const float* ca_w    = (const float*)d_in[6];
    const float* ca_b    = (const float*)d_in[7];

    float *xn, *q, *k, *v, *o, *cf, *sf, *attn;
    cudaGetSymbolAddress((void**)&xn,   g_xn);
    cudaGetSymbolAddress((void**)&q,    g_q);
    cudaGetSymbolAddress((void**)&k,    g_k);
    cudaGetSymbolAddress((void**)&v,    g_v);
    cudaGetSymbolAddress((void**)&o,    g_o);
    cudaGetSymbolAddress((void**)&cf,   g_cf);
    cudaGetSymbolAddress((void**)&sf,   g_sf);
    cudaGetSymbolAddress((void**)&attn, g_attn);

    const int B = BATCH, C = CCH, N = NSP;
    const long long CN = (long long)C * N;      // per-batch feature stride
    const long long NN = (long long)N * N;      // per-batch spatial-attn stride
    const long long WW = (long long)C * C;      // weight matrix / channel-attn stride

    dim3 convGrid(N / 128, C / 128, B);   // (32,4,4)
    dim3 enGrid  (N / 128, N / 128, B);   // (32,32,4)
    dim3 chGrid  (C / 128, C / 128, B);   // (4,4,4)

    // ================= content self-attention =================
    mvn_kernel<<<B * C, 256>>>(content, xn, N);
    // q = W0 @ xn + b0 ; k = W1 @ xn + b1 ; v = W2 @ content + b2
    gemm_kernel<<<convGrid, 256>>>(csa_w + 0 * WW, xn,      q, 0, C, 1, CN, N, 1, CN, csa_b + 0 * C, nullptr, 0, C, N, C);
    gemm_kernel<<<convGrid, 256>>>(csa_w + 1 * WW, xn,      k, 0, C, 1, CN, N, 1, CN, csa_b + 1 * C, nullptr, 0, C, N, C);
    gemm_kernel<<<convGrid, 256>>>(csa_w + 2 * WW, content, v, 0, C, 1, CN, N, 1, CN, csa_b + 2 * C, nullptr, 0, C, N, C);
    // E[i,j] = sum_c q[c,i] k[c,j]  (A = q^T: sam=1, sak=N ; B = k: sbk=N, sbn=1)
    gemm_kernel<<<enGrid, 256>>>(q, k, attn, CN, 1, N, CN, N, 1, NN, nullptr, nullptr, 0, N, N, C);
    softmax_kernel<<<B * N, 256>>>(attn, N);
    // O[c,i] = sum_j v[c,j] attn[i,j]  (A = v: sam=N, sak=1 ; B = attn^T: sbk=1, sbn=N)
    gemm_kernel<<<convGrid, 256>>>(v, attn, o, CN, N, 1, NN, 1, N, CN, nullptr, nullptr, 0, C, N, N);
    // cf = W3 @ O + b3 + content
    gemm_kernel<<<convGrid, 256>>>(csa_w + 3 * WW, o, cf, 0, C, 1, CN, N, 1, CN, csa_b + 3 * C, content, CN, C, N, C);

    // ================= style self-attention (channel attention) =================
    mvn_kernel<<<B * C, 256>>>(style, xn, N);
    gemm_kernel<<<convGrid, 256>>>(ssa_w + 0 * WW, style, q, 0, C, 1, CN, N, 1, CN, ssa_b + 0 * C, nullptr, 0, C, N, C); // f
    gemm_kernel<<<convGrid, 256>>>(ssa_w + 1 * WW, style, k, 0, C, 1, CN, N, 1, CN, ssa_b + 1 * C, nullptr, 0, C, N, C); // g
    gemm_kernel<<<convGrid, 256>>>(ssa_w + 2 * WW, xn,    v, 0, C, 1, CN, N, 1, CN, ssa_b + 2 * C, nullptr, 0, C, N, C); // h
    // E[c,d] = sum_i f[c,i] g[d,i]  (A = f: sam=N, sak=1 ; B = g^T: sbk=1, sbn=N), M=N=C, K=Nsp
    gemm_kernel<<<chGrid, 256>>>(q, k, attn, CN, N, 1, CN, 1, N, WW, nullptr, nullptr, 0, C, C, N);
    softmax_kernel<<<B * C, 256>>>(attn, C);
    // O[c,i] = sum_d attn[d,c] h[d,i]  (A = attn^T: sam=1, sak=C ; B = h: sbk=N, sbn=1)
    gemm_kernel<<<convGrid, 256>>>(attn, v, o, WW, 1, C, CN, N, 1, CN, nullptr, nullptr, 0, C, N, C);
    // sf = W3 @ O + b3 + style
    gemm_kernel<<<convGrid, 256>>>(ssa_w + 3 * WW, o, sf, 0, C, 1, CN, N, 1, CN, ssa_b + 3 * C, style, CN, C, N, C);

    // ================= cross attention =================
    mvn_kernel<<<B * C, 256>>>(cf, xn, N);
    gemm_kernel<<<convGrid, 256>>>(ca_w + 0 * WW, xn, q, 0, C, 1, CN, N, 1, CN, ca_b + 0 * C, nullptr, 0, C, N, C);
    mvn_kernel<<<B * C, 256>>>(sf, xn, N);
    gemm_kernel<<<convGrid, 256>>>(ca_w + 1 * WW, xn, k, 0, C, 1, CN, N, 1, CN, ca_b + 1 * C, nullptr, 0, C, N, C);
    gemm_kernel<<<convGrid, 256>>>(ca_w + 2 * WW, sf, v, 0, C, 1, CN, N, 1, CN, ca_b + 2 * C, nullptr, 0, C, N, C);
    gemm_kernel<<<enGrid, 256>>>(q, k, attn, CN, 1, N, CN, N, 1, NN, nullptr, nullptr, 0, N, N, C);
    softmax_kernel<<<B * N, 256>>>(attn, N);
    gemm_kernel<<<convGrid, 256>>>(v, attn, o, CN, N, 1, NN, 1, N, CN, nullptr, nullptr, 0, C, N, N);
    // result = W3 @ O + b3 + cf  -> d_out
    gemm_kernel<<<convGrid, 256>>>(ca_w + 3 * WW, o, (float*)d_out, 0, C, 1, CN, N, 1, CN, ca_b + 3 * C, cf, CN, C, N, C);
}

// round 2
// speedup vs baseline: 2.6646x; 2.6646x over previous
#include <cuda_runtime.h>
#include <math.h>

#define EPSV 1e-5f

static const int BATCH = 4;
static const int CCH   = 512;
static const int NSP   = 4096;   // H*W

// ---------------- scratch (device globals; no runtime allocation) ----------------
__device__ float g_xn [(size_t)4 * 512 * 4096];
__device__ float g_q  [(size_t)4 * 512 * 4096];
__device__ float g_k  [(size_t)4 * 512 * 4096];
__device__ float g_v  [(size_t)4 * 512 * 4096];
__device__ float g_o  [(size_t)4 * 512 * 4096];
__device__ float g_cf [(size_t)4 * 512 * 4096];
__device__ float g_sf [(size_t)4 * 512 * 4096];
__device__ float g_attn[(size_t)4 * 4096 * 4096];

// ---------------- helpers ----------------
__device__ __forceinline__ unsigned f2tf(float x) {
    unsigned u;
    asm("cvt.rna.tf32.f32 %0, %1;" : "=r"(u) : "f"(x));
    return u;
}

__device__ __forceinline__ void mma8(float* c, const unsigned* a, const unsigned* b) {
    asm volatile(
        "mma.sync.aligned.m16n8k8.row.col.f32.tf32.tf32.f32 "
        "{%0,%1,%2,%3}, {%4,%5,%6,%7}, {%8,%9}, {%0,%1,%2,%3};"
        : "+f"(c[0]), "+f"(c[1]), "+f"(c[2]), "+f"(c[3])
        : "r"(a[0]), "r"(a[1]), "r"(a[2]), "r"(a[3]), "r"(b[0]), "r"(b[1]));
}

// ---------------- MVN: per-row mean/var normalize (unbiased var, ddof=1) ----------------
__global__ void mvn_kernel(const float* __restrict__ x, float* __restrict__ y, int n) {
    const float* xr = x + (size_t)blockIdx.x * n;
    float*       yr = y + (size_t)blockIdx.x * n;
    int tid = threadIdx.x;
    float s = 0.f, s2 = 0.f;
    for (int i = tid; i < n; i += blockDim.x) {
        float v = xr[i];
        s += v; s2 += v * v;
    }
    __shared__ float sh0[256];
    __shared__ float sh1[256];
    sh0[tid] = s; sh1[tid] = s2;
    __syncthreads();
    for (int o = 128; o > 0; o >>= 1) {
        if (tid < o) { sh0[tid] += sh0[tid + o]; sh1[tid] += sh1[tid + o]; }
        __syncthreads();
    }
    float mean = sh0[0] / (float)n;
    float var  = (sh1[0] - (float)n * mean * mean) / (float)(n - 1);
    float inv  = rsqrtf(var + EPSV);
    for (int i = tid; i < n; i += blockDim.x) {
        yr[i] = (xr[i] - mean) * inv;
    }
}

// ---------------- row softmax (in place), row cached in registers ----------------
// Requires n % blockDim.x == 0 and n/blockDim.x <= 16.
__global__ void softmax_kernel(float* __restrict__ data, int n) {
    float* r = data + (size_t)blockIdx.x * n;
    int tid = threadIdx.x;
    int per = n / blockDim.x;       // 16 (spatial) or 2 (channel)
    float buf[16];
    __shared__ float sh[256];

    float m = -1e30f;
#pragma unroll 16
    for (int i = 0; i < 16; i++) {
        if (i < per) {
            float v = r[tid + i * blockDim.x];
            buf[i] = v;
            m = fmaxf(m, v);
        }
    }
    sh[tid] = m; __syncthreads();
    for (int o = 128; o > 0; o >>= 1) {
        if (tid < o) sh[tid] = fmaxf(sh[tid], sh[tid + o]);
        __syncthreads();
    }
    float mx = sh[0];
    __syncthreads();

    float s = 0.f;
#pragma unroll 16
    for (int i = 0; i < 16; i++) {
        if (i < per) {
            float e = __expf(buf[i] - mx);
            buf[i] = e;
            s += e;
        }
    }
    sh[tid] = s; __syncthreads();
    for (int o = 128; o > 0; o >>= 1) {
        if (tid < o) sh[tid] += sh[tid + o];
        __syncthreads();
    }
    float inv = 1.f / sh[0];
#pragma unroll 16
    for (int i = 0; i < 16; i++) {
        if (i < per) r[tid + i * blockDim.x] = buf[i] * inv;
    }
}

// ---------------- TF32 tensor-core batched GEMM, generic strides ----------------
// C[b][m][n] = sum_k A(m,k)*B(k,n) + bias[m] + res[b][m][n]
// A(m,k) = A[b*aBatch + m*sam + k*sak], B(k,n) = B[b*bBatch + k*sbk + n*sbn]
// Requires M%128==0, N%128==0, K%16==0. C/res are row-major [M,N].
__global__ __launch_bounds__(256) void gemm_tc(
    const float* __restrict__ A, const float* __restrict__ Bp, float* __restrict__ C,
    long long aBatch, long long sam, long long sak,
    long long bBatch, long long sbk, long long sbn,
    long long cBatch,
    const float* __restrict__ bias,
    const float* __restrict__ res, long long rBatch,
    int M, int N, int K)
{
    const int BM = 128, BN = 128, BK = 16;
    __shared__ unsigned As[BK][BM + 8];
    __shared__ unsigned Bs[BK][BN + 8];

    int bz = blockIdx.z;
    A  += (long long)bz * aBatch;
    Bp += (long long)bz * bBatch;
    C  += (long long)bz * cBatch;
    if (res) res += (long long)bz * rBatch;

    int tid  = threadIdx.x;
    int lane = tid & 31;
    int warp = tid >> 5;
    int m0 = blockIdx.y * BM;
    int n0 = blockIdx.x * BN;
    int wm = (warp & 1) * 64;   // 2 warps along M
    int wn = (warp >> 1) * 32;  // 4 warps along N

    bool aK = (sak == 1);
    bool bK = (sbk == 1);

    // per-thread global-load descriptors (8 elems per operand per tile)
    int a_kk, a_mm; long long aOff, aStep;
    if (aK) { a_kk = tid & 15; a_mm = tid >> 4;
              aOff = (long long)(m0 + a_mm) * sam + a_kk; aStep = 16 * sam; }
    else    { a_mm = tid & 127; a_kk = tid >> 7;
              aOff = (long long)(m0 + a_mm) * sam + (long long)a_kk * sak; aStep = 2 * sak; }
    int b_kk, b_nn; long long bOff, bStep;
    if (bK) { b_kk = tid & 15; b_nn = tid >> 4;
              bOff = (long long)(n0 + b_nn) * sbn + b_kk; bStep = 16 * sbn; }
    else    { b_nn = tid & 127; b_kk = tid >> 7;
              bOff = (long long)(n0 + b_nn) * sbn + (long long)b_kk * sbk; bStep = 2 * sbk; }

    float acc[4][4][4];
#pragma unroll
    for (int mt = 0; mt < 4; mt++)
#pragma unroll
        for (int nt = 0; nt < 4; nt++)
#pragma unroll
            for (int i = 0; i < 4; i++) acc[mt][nt][i] = 0.f;

    float ra[8], rb[8];
    // prefetch first tile
#pragma unroll
    for (int i = 0; i < 8; i++) ra[i] = A[aOff + i * aStep];
#pragma unroll
    for (int i = 0; i < 8; i++) rb[i] = Bp[bOff + i * bStep];

    for (int k0 = 0; k0 < K; k0 += BK) {
        // stage registers -> smem (tf32 converted)
        if (aK) {
#pragma unroll
            for (int i = 0; i < 8; i++) As[a_kk][a_mm + 16 * i] = f2tf(ra[i]);
        } else {
#pragma unroll
            for (int i = 0; i < 8; i++) As[a_kk + 2 * i][a_mm] = f2tf(ra[i]);
        }
        if (bK) {
#pragma unroll
            for (int i = 0; i < 8; i++) Bs[b_kk][b_nn + 16 * i] = f2tf(rb[i]);
        } else {
#pragma unroll
            for (int i = 0; i < 8; i++) Bs[b_kk + 2 * i][b_nn] = f2tf(rb[i]);
        }
        __syncthreads();

        // prefetch next tile (in flight during compute)
        aOff += (long long)BK * sak;
        bOff += (long long)BK * sbk;
        if (k0 + BK < K) {
#pragma unroll
            for (int i = 0; i < 8; i++) ra[i] = A[aOff + i * aStep];
#pragma unroll
            for (int i = 0; i < 8; i++) rb[i] = Bp[bOff + i * bStep];
        }

        // compute 2 k-slices of 8
#pragma unroll
        for (int ks = 0; ks < BK; ks += 8) {
            unsigned af[4][4], bf[4][2];
            int r = lane >> 2;
            int c = ks + (lane & 3);
#pragma unroll
            for (int mt = 0; mt < 4; mt++) {
                int m = wm + mt * 16 + r;
                af[mt][0] = As[c][m];
                af[mt][1] = As[c][m + 8];
                af[mt][2] = As[c + 4][m];
                af[mt][3] = As[c + 4][m + 8];
            }
#pragma unroll
            for (int nt = 0; nt < 4; nt++) {
                int n = wn + nt * 8 + r;
                bf[nt][0] = Bs[c][n];
                bf[nt][1] = Bs[c + 4][n];
            }
#pragma unroll
            for (int mt = 0; mt < 4; mt++)
#pragma unroll
                for (int nt = 0; nt < 4; nt++)
                    mma8(acc[mt][nt], af[mt], bf[nt]);
        }
        __syncthreads();
    }

    // epilogue: bias + residual, float2 stores
#pragma unroll
    for (int mt = 0; mt < 4; mt++) {
        int row = m0 + wm + mt * 16 + (lane >> 2);
        float bi0 = bias ? bias[row]     : 0.f;
        float bi1 = bias ? bias[row + 8] : 0.f;
#pragma unroll
        for (int nt = 0; nt < 4; nt++) {
            int col = n0 + wn + nt * 8 + 2 * (lane & 3);
            float2 v0 = make_float2(acc[mt][nt][0] + bi0, acc[mt][nt][1] + bi0);
            float2 v1 = make_float2(acc[mt][nt][2] + bi1, acc[mt][nt][3] + bi1);
            if (res) {
                float2 r0 = *(const float2*)(res + (long long)row * N + col);
                float2 r1 = *(const float2*)(res + (long long)(row + 8) * N + col);
                v0.x += r0.x; v0.y += r0.y;
                v1.x += r1.x; v1.y += r1.y;
            }
            *(float2*)(C + (long long)row * N + col)       = v0;
            *(float2*)(C + (long long)(row + 8) * N + col) = v1;
        }
    }
}

// ---------------- orchestration ----------------
extern "C" void kernel_launch(void* const* d_in, const int* in_sizes, int n_in,
                              void* d_out, int out_size) {
    const float* content = (const float*)d_in[0];
    const float* style   = (const float*)d_in[1];
    const float* csa_w   = (const float*)d_in[2];
    const float* csa_b   = (const float*)d_in[3];
    const float* ssa_w   = (const float*)d_in[4];
    const float* ssa_b   = (const float*)d_in[5];
    const float* ca_w    = (const float*)d_in[6];
    const float* ca_b    = (const float*)d_in[7];

    float *xn, *q, *k, *v, *o, *cf, *sf, *attn;
    cudaGetSymbolAddress((void**)&xn,   g_xn);
    cudaGetSymbolAddress((void**)&q,    g_q);
    cudaGetSymbolAddress((void**)&k,    g_k);
    cudaGetSymbolAddress((void**)&v,    g_v);
    cudaGetSymbolAddress((void**)&o,    g_o);
    cudaGetSymbolAddress((void**)&cf,   g_cf);
    cudaGetSymbolAddress((void**)&sf,   g_sf);
    cudaGetSymbolAddress((void**)&attn, g_attn);

    const int B = BATCH, C = CCH, N = NSP;
    const long long CN = (long long)C * N;
    const long long NN = (long long)N * N;
    const long long WW = (long long)C * C;

    dim3 convGrid(N / 128, C / 128, B);   // (32,4,4)
    dim3 enGrid  (N / 128, N / 128, B);   // (32,32,4)
    dim3 chGrid  (C / 128, C / 128, B);   // (4,4,4)

    // ================= content self-attention =================
    mvn_kernel<<<B * C, 256>>>(content, xn, N);
    gemm_tc<<<convGrid, 256>>>(csa_w + 0 * WW, xn,      q, 0, C, 1, CN, N, 1, CN, csa_b + 0 * C, nullptr, 0, C, N, C);
    gemm_tc<<<convGrid, 256>>>(csa_w + 1 * WW, xn,      k, 0, C, 1, CN, N, 1, CN, csa_b + 1 * C, nullptr, 0, C, N, C);
    gemm_tc<<<convGrid, 256>>>(csa_w + 2 * WW, content, v, 0, C, 1, CN, N, 1, CN, csa_b + 2 * C, nullptr, 0, C, N, C);
    // E[i,j] = sum_c q[c,i] k[c,j]
    gemm_tc<<<enGrid, 256>>>(q, k, attn, CN, 1, N, CN, N, 1, NN, nullptr, nullptr, 0, N, N, C);
    softmax_kernel<<<B * N, 256>>>(attn, N);
    // O[c,i] = sum_j v[c,j] attn[i,j]
    gemm_tc<<<convGrid, 256>>>(v, attn, o, CN, N, 1, NN, 1, N, CN, nullptr, nullptr, 0, C, N, N);
    gemm_tc<<<convGrid, 256>>>(csa_w + 3 * WW, o, cf, 0, C, 1, CN, N, 1, CN, csa_b + 3 * C, content, CN, C, N, C);

    // ================= style self-attention (channel attention) =================
    mvn_kernel<<<B * C, 256>>>(style, xn, N);
    gemm_tc<<<convGrid, 256>>>(ssa_w + 0 * WW, style, q, 0, C, 1, CN, N, 1, CN, ssa_b + 0 * C, nullptr, 0, C, N, C); // f
    gemm_tc<<<convGrid, 256>>>(ssa_w + 1 * WW, style, k, 0, C, 1, CN, N, 1, CN, ssa_b + 1 * C, nullptr, 0, C, N, C); // g
    gemm_tc<<<convGrid, 256>>>(ssa_w + 2 * WW, xn,    v, 0, C, 1, CN, N, 1, CN, ssa_b + 2 * C, nullptr, 0, C, N, C); // h
    // E[c,d] = sum_i f[c,i] g[d,i]
    gemm_tc<<<chGrid, 256>>>(q, k, attn, CN, N, 1, CN, 1, N, WW, nullptr, nullptr, 0, C, C, N);
    softmax_kernel<<<B * C, 256>>>(attn, C);
    // O[c,i] = sum_d attn[d,c] h[d,i]
    gemm_tc<<<convGrid, 256>>>(attn, v, o, WW, 1, C, CN, N, 1, CN, nullptr, nullptr, 0, C, N, C);
    gemm_tc<<<convGrid, 256>>>(ssa_w + 3 * WW, o, sf, 0, C, 1, CN, N, 1, CN, ssa_b + 3 * C, style, CN, C, N, C);

    // ================= cross attention =================
    mvn_kernel<<<B * C, 256>>>(cf, xn, N);
    gemm_tc<<<convGrid, 256>>>(ca_w + 0 * WW, xn, q, 0, C, 1, CN, N, 1, CN, ca_b + 0 * C, nullptr, 0, C, N, C);
    mvn_kernel<<<B * C, 256>>>(sf, xn, N);
    gemm_tc<<<convGrid, 256>>>(ca_w + 1 * WW, xn, k, 0, C, 1, CN, N, 1, CN, ca_b + 1 * C, nullptr, 0, C, N, C);
    gemm_tc<<<convGrid, 256>>>(ca_w + 2 * WW, sf, v, 0, C, 1, CN, N, 1, CN, ca_b + 2 * C, nullptr, 0, C, N, C);
    gemm_tc<<<enGrid, 256>>>(q, k, attn, CN, 1, N, CN, N, 1, NN, nullptr, nullptr, 0, N, N, C);
    softmax_kernel<<<B * N, 256>>>(attn, N);
    gemm_tc<<<convGrid, 256>>>(v, attn, o, CN, N, 1, NN, 1, N, CN, nullptr, nullptr, 0, C, N, N);
    gemm_tc<<<convGrid, 256>>>(ca_w + 3 * WW, o, (float*)d_out, 0, C, 1, CN, N, 1, CN, ca_b + 3 * C, cf, CN, C, N, C);
}

// round 3
// speedup vs baseline: 2.8574x; 1.0724x over previous
#include <cuda_runtime.h>
#include <math.h>

#define EPSV 1e-5f

static const int BATCH = 4;
static const int CCH   = 512;
static const int NSP   = 4096;   // H*W

// ---------------- scratch (device globals; no runtime allocation) ----------------
__device__ float g_xn [(size_t)4 * 512 * 4096];
__device__ float g_q  [(size_t)4 * 512 * 4096];
__device__ float g_k  [(size_t)4 * 512 * 4096];
__device__ float g_v  [(size_t)4 * 512 * 4096];
__device__ float g_o  [(size_t)4 * 512 * 4096];
__device__ float g_cf [(size_t)4 * 512 * 4096];
__device__ float g_sf [(size_t)4 * 512 * 4096];
__device__ float g_attn[(size_t)4 * 4096 * 4096];

// ---------------- helpers ----------------
__device__ __forceinline__ unsigned f2tf(float x) {
    unsigned u;
    asm("cvt.rna.tf32.f32 %0, %1;" : "=r"(u) : "f"(x));
    return u;
}

__device__ __forceinline__ void mma8(float* c, const unsigned* a, const unsigned* b) {
    asm volatile(
        "mma.sync.aligned.m16n8k8.row.col.f32.tf32.tf32.f32 "
        "{%0,%1,%2,%3}, {%4,%5,%6,%7}, {%8,%9}, {%0,%1,%2,%3};"
        : "+f"(c[0]), "+f"(c[1]), "+f"(c[2]), "+f"(c[3])
        : "r"(a[0]), "r"(a[1]), "r"(a[2]), "r"(a[3]), "r"(b[0]), "r"(b[1]));
}

// ---------------- MVN: per-row mean/var normalize (unbiased var, ddof=1) ----------------
__global__ void mvn_kernel(const float* __restrict__ x, float* __restrict__ y, int n) {
    const float* xr = x + (size_t)blockIdx.x * n;
    float*       yr = y + (size_t)blockIdx.x * n;
    int tid = threadIdx.x;
    float s = 0.f, s2 = 0.f;
    for (int i = tid; i < n; i += blockDim.x) {
        float v = xr[i];
        s += v; s2 += v * v;
    }
    __shared__ float sh0[256];
    __shared__ float sh1[256];
    sh0[tid] = s; sh1[tid] = s2;
    __syncthreads();
    for (int o = 128; o > 0; o >>= 1) {
        if (tid < o) { sh0[tid] += sh0[tid + o]; sh1[tid] += sh1[tid + o]; }
        __syncthreads();
    }
    float mean = sh0[0] / (float)n;
    float var  = (sh1[0] - (float)n * mean * mean) / (float)(n - 1);
    float inv  = rsqrtf(var + EPSV);
    for (int i = tid; i < n; i += blockDim.x) {
        yr[i] = (xr[i] - mean) * inv;
    }
}

// ---------------- row softmax (in place), row cached in registers ----------------
__global__ void softmax_kernel(float* __restrict__ data, int n) {
    float* r = data + (size_t)blockIdx.x * n;
    int tid = threadIdx.x;
    int per = n / blockDim.x;       // 16 (spatial) or 2 (channel)
    float buf[16];
    __shared__ float sh[256];

    float m = -1e30f;
#pragma unroll 16
    for (int i = 0; i < 16; i++) {
        if (i < per) {
            float v = r[tid + i * blockDim.x];
            buf[i] = v;
            m = fmaxf(m, v);
        }
    }
    sh[tid] = m; __syncthreads();
    for (int o = 128; o > 0; o >>= 1) {
        if (tid < o) sh[tid] = fmaxf(sh[tid], sh[tid + o]);
        __syncthreads();
    }
    float mx = sh[0];
    __syncthreads();

    float s = 0.f;
#pragma unroll 16
    for (int i = 0; i < 16; i++) {
        if (i < per) {
            float e = __expf(buf[i] - mx);
            buf[i] = e;
            s += e;
        }
    }
    sh[tid] = s; __syncthreads();
    for (int o = 128; o > 0; o >>= 1) {
        if (tid < o) sh[tid] += sh[tid + o];
        __syncthreads();
    }
    float inv = 1.f / sh[0];
#pragma unroll 16
    for (int i = 0; i < 16; i++) {
        if (i < per) r[tid + i * blockDim.x] = buf[i] * inv;
    }
}

// ---------------- TF32 tensor-core batched GEMM, generic strides ----------------
// Paired-k smem layout: As2[p][m] = float2( elem(k), elem(k+4) ),
//   p = ((k>>3)<<2) | (k&3),  component = (k>>2)&1.
// Fragment loads become LDS.64 with compile-time offsets.
// Requires M%128==0, N%128==0, K%16==0.
#define RS 132   // row stride in float2 units (128 + 4 pad); RS%16==4 -> conflict-free
__global__ __launch_bounds__(256) void gemm_tc(
    const float* __restrict__ A, const float* __restrict__ Bp, float* __restrict__ C,
    long long aBatch, long long sam, long long sak,
    long long bBatch, long long sbk, long long sbn,
    long long cBatch,
    const float* __restrict__ bias,
    const float* __restrict__ res, long long rBatch,
    int M, int N, int K)
{
    const int BM = 128, BK = 16;
    __shared__ float2 As2[8][RS];
    __shared__ float2 Bs2[8][RS];

    int bz = blockIdx.z;
    A  += (long long)bz * aBatch;
    Bp += (long long)bz * bBatch;
    C  += (long long)bz * cBatch;
    if (res) res += (long long)bz * rBatch;

    int tid  = threadIdx.x;
    int lane = tid & 31;
    int warp = tid >> 5;
    int m0 = blockIdx.y * BM;
    int n0 = blockIdx.x * BM;
    int wm = (warp & 1) * 64;   // 2 warps along M
    int wn = (warp >> 1) * 32;  // 4 warps along N

    bool aK = (sak == 1);
    bool bK = (sbk == 1);

    // per-thread global-load descriptors (8 elems per operand per tile)
    int a_kk, a_mm; long long aOff, aStep;
    if (aK) { a_kk = tid & 15; a_mm = tid >> 4;
              aOff = (long long)(m0 + a_mm) * sam + a_kk; aStep = 16 * sam; }
    else    { a_mm = tid & 127; a_kk = tid >> 7;
              aOff = (long long)(m0 + a_mm) * sam + (long long)a_kk * sak; aStep = 2 * sak; }
    int b_kk, b_nn; long long bOff, bStep;
    if (bK) { b_kk = tid & 15; b_nn = tid >> 4;
              bOff = (long long)(n0 + b_nn) * sbn + b_kk; bStep = 16 * sbn; }
    else    { b_nn = tid & 127; b_kk = tid >> 7;
              bOff = (long long)(n0 + b_nn) * sbn + (long long)b_kk * sbk; bStep = 2 * sbk; }

    // precomputed smem write targets
    int ap = ((a_kk >> 3) << 2) | (a_kk & 3);
    int ah = (a_kk >> 2) & 1;
    int bp = ((b_kk >> 3) << 2) | (b_kk & 3);
    int bh = (b_kk >> 2) & 1;

    // precomputed fragment read indices (float2 units)
    int r = lane >> 2;
    const unsigned aIdx = (unsigned)((lane & 3) * RS + wm + r);
    const unsigned bIdx = (unsigned)((lane & 3) * RS + wn + r);
    const float2* a2p = &As2[0][0];
    const float2* b2p = &Bs2[0][0];

    float acc[4][4][4];
#pragma unroll
    for (int mt = 0; mt < 4; mt++)
#pragma unroll
        for (int nt = 0; nt < 4; nt++)
#pragma unroll
            for (int i = 0; i < 4; i++) acc[mt][nt][i] = 0.f;

    float ra[8], rb[8];
#pragma unroll
    for (int i = 0; i < 8; i++) ra[i] = A[aOff + i * aStep];
#pragma unroll
    for (int i = 0; i < 8; i++) rb[i] = Bp[bOff + i * bStep];

    for (int k0 = 0; k0 < K; k0 += BK) {
        // stage registers -> smem (tf32, paired-k layout)
        if (aK) {
            unsigned* dst = (unsigned*)&As2[ap][a_mm] + ah;
#pragma unroll
            for (int i = 0; i < 8; i++) dst[32 * i] = f2tf(ra[i]);
        } else {
#pragma unroll
            for (int i = 0; i < 8; i++) {
                int k = a_kk + 2 * i;
                int p = ((k >> 3) << 2) | (k & 3);
                int h = (k >> 2) & 1;
                ((unsigned*)&As2[p][a_mm])[h] = f2tf(ra[i]);
            }
        }
        if (bK) {
            unsigned* dst = (unsigned*)&Bs2[bp][b_nn] + bh;
#pragma unroll
            for (int i = 0; i < 8; i++) dst[32 * i] = f2tf(rb[i]);
        } else {
#pragma unroll
            for (int i = 0; i < 8; i++) {
                int k = b_kk + 2 * i;
                int p = ((k >> 3) << 2) | (k & 3);
                int h = (k >> 2) & 1;
                ((unsigned*)&Bs2[p][b_nn])[h] = f2tf(rb[i]);
            }
        }
        __syncthreads();

        // prefetch next tile (in flight during compute)
        aOff += (long long)BK * sak;
        bOff += (long long)BK * sbk;
        if (k0 + BK < K) {
#pragma unroll
            for (int i = 0; i < 8; i++) ra[i] = A[aOff + i * aStep];
#pragma unroll
            for (int i = 0; i < 8; i++) rb[i] = Bp[bOff + i * bStep];
        }

        // compute 2 k-slices of 8 (slice ks uses rows p = 4*ks .. 4*ks+3)
#pragma unroll
        for (int ks = 0; ks < 2; ks++) {
            const unsigned off = ks * (4u * RS);
            unsigned af[4][4], bf[4][2];
#pragma unroll
            for (int mt = 0; mt < 4; mt++) {
                float2 lo = a2p[aIdx + off + mt * 16];
                float2 hi = a2p[aIdx + off + mt * 16 + 8];
                af[mt][0] = __float_as_uint(lo.x);
                af[mt][1] = __float_as_uint(hi.x);
                af[mt][2] = __float_as_uint(lo.y);
                af[mt][3] = __float_as_uint(hi.y);
            }
#pragma unroll
            for (int nt = 0; nt < 4; nt++) {
                float2 pb = b2p[bIdx + off + nt * 8];
                bf[nt][0] = __float_as_uint(pb.x);
                bf[nt][1] = __float_as_uint(pb.y);
            }
#pragma unroll
            for (int mt = 0; mt < 4; mt++)
#pragma unroll
                for (int nt = 0; nt < 4; nt++)
                    mma8(acc[mt][nt], af[mt], bf[nt]);
        }
        __syncthreads();
    }

    // epilogue: bias + residual, float2 stores
#pragma unroll
    for (int mt = 0; mt < 4; mt++) {
        int row = m0 + wm + mt * 16 + (lane >> 2);
        float bi0 = bias ? bias[row]     : 0.f;
        float bi1 = bias ? bias[row + 8] : 0.f;
#pragma unroll
        for (int nt = 0; nt < 4; nt++) {
            int col = n0 + wn + nt * 8 + 2 * (lane & 3);
            float2 v0 = make_float2(acc[mt][nt][0] + bi0, acc[mt][nt][1] + bi0);
            float2 v1 = make_float2(acc[mt][nt][2] + bi1, acc[mt][nt][3] + bi1);
            if (res) {
                float2 r0 = *(const float2*)(res + (long long)row * N + col);
                float2 r1 = *(const float2*)(res + (long long)(row + 8) * N + col);
                v0.x += r0.x; v0.y += r0.y;
                v1.x += r1.x; v1.y += r1.y;
            }
            *(float2*)(C + (long long)row * N + col)       = v0;
            *(float2*)(C + (long long)(row + 8) * N + col) = v1;
        }
    }
}

// ---------------- orchestration ----------------
extern "C" void kernel_launch(void* const* d_in, const int* in_sizes, int n_in,
                              void* d_out, int out_size) {
    const float* content = (const float*)d_in[0];
    const float* style   = (const float*)d_in[1];
    const float* csa_w   = (const float*)d_in[2];
    const float* csa_b   = (const float*)d_in[3];
    const float* ssa_w   = (const float*)d_in[4];
    const float* ssa_b   = (const float*)d_in[5];
    const float* ca_w    = (const float*)d_in[6];
    const float* ca_b    = (const float*)d_in[7];

    float *xn, *q, *k, *v, *o, *cf, *sf, *attn;
    cudaGetSymbolAddress((void**)&xn,   g_xn);
    cudaGetSymbolAddress((void**)&q,    g_q);
    cudaGetSymbolAddress((void**)&k,    g_k);
    cudaGetSymbolAddress((void**)&v,    g_v);
    cudaGetSymbolAddress((void**)&o,    g_o);
    cudaGetSymbolAddress((void**)&cf,   g_cf);
    cudaGetSymbolAddress((void**)&sf,   g_sf);
    cudaGetSymbolAddress((void**)&attn, g_attn);

    const int B = BATCH, C = CCH, N = NSP;
    const long long CN = (long long)C * N;
    const long long NN = (long long)N * N;
    const long long WW = (long long)C * C;

    dim3 convGrid(N / 128, C / 128, B);   // (32,4,4)
    dim3 enGrid  (N / 128, N / 128, B);   // (32,32,4)
    dim3 chGrid  (C / 128, C / 128, B);   // (4,4,4)

    // ================= content self-attention =================
    mvn_kernel<<<B * C, 256>>>(content, xn, N);
    gemm_tc<<<convGrid, 256>>>(csa_w + 0 * WW, xn,      q, 0, C, 1, CN, N, 1, CN, csa_b + 0 * C, nullptr, 0, C, N, C);
    gemm_tc<<<convGrid, 256>>>(csa_w + 1 * WW, xn,      k, 0, C, 1, CN, N, 1, CN, csa_b + 1 * C, nullptr, 0, C, N, C);
    gemm_tc<<<convGrid, 256>>>(csa_w + 2 * WW, content, v, 0, C, 1, CN, N, 1, CN, csa_b + 2 * C, nullptr, 0, C, N, C);
    // E[i,j] = sum_c q[c,i] k[c,j]
    gemm_tc<<<enGrid, 256>>>(q, k, attn, CN, 1, N, CN, N, 1, NN, nullptr, nullptr, 0, N, N, C);
    softmax_kernel<<<B * N, 256>>>(attn, N);
    // O[c,i] = sum_j v[c,j] attn[i,j]
    gemm_tc<<<convGrid, 256>>>(v, attn, o, CN, N, 1, NN, 1, N, CN, nullptr, nullptr, 0, C, N, N);
    gemm_tc<<<convGrid, 256>>>(csa_w + 3 * WW, o, cf, 0, C, 1, CN, N, 1, CN, csa_b + 3 * C, content, CN, C, N, C);

    // ================= style self-attention (channel attention) =================
    mvn_kernel<<<B * C, 256>>>(style, xn, N);
    gemm_tc<<<convGrid, 256>>>(ssa_w + 0 * WW, style, q, 0, C, 1, CN, N, 1, CN, ssa_b + 0 * C, nullptr, 0, C, N, C); // f
    gemm_tc<<<convGrid, 256>>>(ssa_w + 1 * WW, style, k, 0, C, 1, CN, N, 1, CN, ssa_b + 1 * C, nullptr, 0, C, N, C); // g
    gemm_tc<<<convGrid, 256>>>(ssa_w + 2 * WW, xn,    v, 0, C, 1, CN, N, 1, CN, ssa_b + 2 * C, nullptr, 0, C, N, C); // h
    // E[c,d] = sum_i f[c,i] g[d,i]
    gemm_tc<<<chGrid, 256>>>(q, k, attn, CN, N, 1, CN, 1, N, WW, nullptr, nullptr, 0, C, C, N);
    softmax_kernel<<<B * C, 256>>>(attn, C);
    // O[c,i] = sum_d attn[d,c] h[d,i]
    gemm_tc<<<convGrid, 256>>>(attn, v, o, WW, 1, C, CN, N, 1, CN, nullptr, nullptr, 0, C, N, C);
    gemm_tc<<<convGrid, 256>>>(ssa_w + 3 * WW, o, sf, 0, C, 1, CN, N, 1, CN, ssa_b + 3 * C, style, CN, C, N, C);

    // ================= cross attention =================
    mvn_kernel<<<B * C, 256>>>(cf, xn, N);
    gemm_tc<<<convGrid, 256>>>(ca_w + 0 * WW, xn, q, 0, C, 1, CN, N, 1, CN, ca_b + 0 * C, nullptr, 0, C, N, C);
    mvn_kernel<<<B * C, 256>>>(sf, xn, N);
    gemm_tc<<<convGrid, 256>>>(ca_w + 1 * WW, xn, k, 0, C, 1, CN, N, 1, CN, ca_b + 1 * C, nullptr, 0, C, N, C);
    gemm_tc<<<convGrid, 256>>>(ca_w + 2 * WW, sf, v, 0, C, 1, CN, N, 1, CN, ca_b + 2 * C, nullptr, 0, C, N, C);
    gemm_tc<<<enGrid, 256>>>(q, k, attn, CN, 1, N, CN, N, 1, NN, nullptr, nullptr, 0, N, N, C);
    softmax_kernel<<<B * N, 256>>>(attn, N);
    gemm_tc<<<convGrid, 256>>>(v, attn, o, CN, N, 1, NN, 1, N, CN, nullptr, nullptr, 0, C, N, N);
    gemm_tc<<<convGrid, 256>>>(ca_w + 3 * WW, o, (float*)d_out, 0, C, 1, CN, N, 1, CN, ca_b + 3 * C, cf, CN, C, N, C);
}